// round 9
// baseline (speedup 1.0000x reference)
#include <cuda_runtime.h>
#include <cuda_bf16.h>
#include <math.h>
#include <stdint.h>

#define NB 4
#define LQ 2048
#define SK 4096
#define CH 256
#define NH 8
#define DH 32
#define HID 1024
#define NLROWS (NB*LQ)      // 8192
#define NSROWS (NB*SK)      // 16384

// ---------------- scratch (device globals; no runtime alloc) ----------------
__device__ float g_q   [NLROWS*CH];
__device__ float g_k   [NLROWS*CH];
__device__ float g_v   [NLROWS*CH];
__device__ float g_t1  [NLROWS*CH];
__device__ float g_t2  [NLROWS*CH];
__device__ float g_kv  [NB*NH*DH*DH];
__device__ float g_ksum[NB*NH*DH];
__device__ float g_kvp [NB*NH*8*DH*DH];
__device__ float g_ksp [NB*NH*8*DH];

__device__ __nv_bfloat16 g_xb1 [NLROWS*CH];
__device__ __nv_bfloat16 g_xb2 [NLROWS*CH];
__device__ __nv_bfloat16 g_laob[NLROWS*CH];
__device__ __nv_bfloat16 g_memb[NSROWS*CH];
__device__ __nv_bfloat16 g_cqb [NLROWS*CH];
__device__ __nv_bfloat16 g_ckb [NSROWS*CH];
__device__ __nv_bfloat16 g_cvb [NSROWS*CH];
__device__ __nv_bfloat16 g_cvt [NB*NH*DH*SK];
__device__ __nv_bfloat16 g_cob [NLROWS*CH];
__device__ __nv_bfloat16 g_hb  [NLROWS*HID];
__device__ __nv_bfloat16 g_h2b [NLROWS*HID];
__device__ __nv_bfloat16 g_wts [8*CH*CH + CH*HID + HID*CH];

#define WT_WQ   0
#define WT_WK   (1*CH*CH)
#define WT_WV   (2*CH*CH)
#define WT_WM   (3*CH*CH)
#define WT_CWQ  (4*CH*CH)
#define WT_CWK  (5*CH*CH)
#define WT_CWV  (6*CH*CH)
#define WT_CWO  (7*CH*CH)
#define WT_MW1  (8*CH*CH)
#define WT_MW2  (8*CH*CH + CH*HID)

// ---------------- helpers ----------------
__device__ __forceinline__ void mma_bf16(float* c, uint32_t a0, uint32_t a1, uint32_t a2, uint32_t a3,
                                         uint32_t b0, uint32_t b1)
{
    asm volatile("mma.sync.aligned.m16n8k16.row.col.f32.bf16.bf16.f32 "
                 "{%0,%1,%2,%3}, {%4,%5,%6,%7}, {%8,%9}, {%0,%1,%2,%3};"
                 : "+f"(c[0]), "+f"(c[1]), "+f"(c[2]), "+f"(c[3])
                 : "r"(a0), "r"(a1), "r"(a2), "r"(a3), "r"(b0), "r"(b1));
}

__device__ __forceinline__ void ldsm4(uint32_t& r0, uint32_t& r1, uint32_t& r2, uint32_t& r3, uint32_t a)
{
    asm volatile("ldmatrix.sync.aligned.m8n8.x4.shared.b16 {%0,%1,%2,%3}, [%4];"
                 : "=r"(r0), "=r"(r1), "=r"(r2), "=r"(r3) : "r"(a));
}

__device__ __forceinline__ uint32_t pack_bf16(float lo, float hi)
{
    __nv_bfloat162 t = __float22bfloat162_rn(make_float2(lo, hi));
    return *(uint32_t*)&t;
}

__device__ __forceinline__ uint32_t saddr(const void* p)
{
    return (uint32_t)__cvta_generic_to_shared(p);
}

#define CP16(dst, src) asm volatile("cp.async.cg.shared.global [%0], [%1], 16;" :: "r"(dst), "l"(src))
#define CP_COMMIT()    asm volatile("cp.async.commit_group;")
#define CP_WAIT0()     asm volatile("cp.async.wait_group 0;")
#define CP_WAIT1()     asm volatile("cp.async.wait_group 1;")

// ---------------- fused weight transpose: all 10 weights in one launch ----------------
struct WSrc { const float* p[10]; };

__global__ void wtrans_all(WSrc ws, __nv_bfloat16* __restrict__ dst)
{
    __shared__ float t[32][33];
    int bid = blockIdx.x;
    int w, kt, nt;
    if (bid < 512)       { w = bid >> 6;  int r = bid & 63;   kt = r >> 3; nt = r & 7;  }
    else if (bid < 768)  { w = 8;         int r = bid - 512;  kt = r >> 5; nt = r & 31; }
    else                 { w = 9;         int r = bid - 768;  kt = r >> 3; nt = r & 7;  }
    int Kd = (w == 9) ? 1024 : 256;
    int Nd = (w == 8) ? 1024 : 256;
    size_t doff = (w < 8) ? (size_t)w * (CH*CH) : (w == 8 ? (size_t)8*CH*CH : (size_t)8*CH*CH + CH*HID);
    const float* W = ws.p[w];
    __nv_bfloat16* Wt = dst + doff;
    int n0 = nt * 32, k0 = kt * 32;
    int tx = threadIdx.x, ty = threadIdx.y;   // (32,8)
    #pragma unroll
    for (int i = 0; i < 4; i++)
        t[ty + i * 8][tx] = W[(size_t)(k0 + ty + i * 8) * Nd + n0 + tx];
    __syncthreads();
    #pragma unroll
    for (int i = 0; i < 4; i++)
        Wt[(size_t)(n0 + ty + i * 8) * Kd + k0 + tx] = __float2bfloat16(t[tx][ty + i * 8]);
}

// ---------------- LayerNorm: bf16 outputs (y, optional y2=y+addp) ----------------
__global__ void ln_kernel(const float* __restrict__ x, const float* __restrict__ g,
                          const float* __restrict__ b, const float* __restrict__ addp,
                          __nv_bfloat16* __restrict__ y, __nv_bfloat16* __restrict__ y2)
{
    int row = blockIdx.x, tid = threadIdx.x;
    size_t base = (size_t)row * CH;
    float v = x[base + tid];
    float s1 = v, s2 = v * v;
    #pragma unroll
    for (int off = 16; off > 0; off >>= 1) {
        s1 += __shfl_xor_sync(0xffffffffu, s1, off);
        s2 += __shfl_xor_sync(0xffffffffu, s2, off);
    }
    __shared__ float r1[8], r2[8];
    int warp = tid >> 5, lane = tid & 31;
    if (lane == 0) { r1[warp] = s1; r2[warp] = s2; }
    __syncthreads();
    float t1 = 0.f, t2 = 0.f;
    #pragma unroll
    for (int w = 0; w < 8; w++) { t1 += r1[w]; t2 += r2[w]; }
    float mean = t1 * (1.f / CH);
    float var  = t2 * (1.f / CH) - mean * mean;
    float inv  = rsqrtf(var + 1e-5f);
    float out  = (v - mean) * inv * g[tid] + b[tid];
    y[base + tid] = __float2bfloat16(out);
    if (y2) y2[base + tid] = __float2bfloat16(out + addp[base + tid]);
}

// ---------------- bf16 GEMM v3: single-shot K phase (KC=256), no inner k-loop ----------------
// BM=64, BN=64, 256 threads (8 warps: 4m x 2n, warp tile 16x32).
// Whole 256-wide K phase resident in smem; ONE wait + ONE sync, then 64 MMAs/warp.
// K=1024 (mw2): 4 phases, 2-stage double buffer.
// EPI 0: +bias ; EPI 1: elu(z)+1 ; EPI 2: +bias +res.  OUTBF: write bf16.
#define KC 256
#define TSTRIDE 264                      // row stride (elems); 528B -> ldmatrix conflict-free
#define TILE_E (64 * TSTRIDE)            // elems per tile

template<int EPI, bool OUTBF, bool DUAL>
__global__ void __launch_bounds__(256)
gemm_v3(const __nv_bfloat16* __restrict__ X, const __nv_bfloat16* __restrict__ Wt,
        const float* __restrict__ bias, const float* __restrict__ bias2,
        const float* __restrict__ res,
        void* __restrict__ Yv, void* __restrict__ Yv2,
        int M, int K, int NOUT)
{
    extern __shared__ __nv_bfloat16 sm[];
    const int PH = K / KC;
    const int ST = (PH > 1) ? 2 : 1;
    __nv_bfloat16* Asm = sm;
    __nv_bfloat16* Bsm = sm + ST * TILE_E;

    int tid = threadIdx.x;
    int lane = tid & 31, wid = tid >> 5;
    int qd = lane & 3, rg = lane >> 2;
    int wm = wid >> 1, wn = wid & 1;
    int row0 = blockIdx.y * 64, col0 = blockIdx.x * 64;

    float acc[4][4];
    #pragma unroll
    for (int nj = 0; nj < 4; nj++)
        #pragma unroll
        for (int e = 0; e < 4; e++) acc[nj][e] = 0.f;

    // ldmatrix lane offsets (elements)
    int laneA = ((lane & 7) + ((lane >> 3) & 1) * 8) * TSTRIDE + (lane >> 4) * 8;
    int laneB = ((lane & 7) + (lane >> 4) * 8) * TSTRIDE + ((lane >> 3) & 1) * 8;

    // fill helper (8 A-chunks + 8 B-chunks per thread)
    auto fill = [&](int st, int ph) {
        int kbase = ph * KC;
        #pragma unroll
        for (int j = 0; j < 8; j++) {
            int idx = tid + j * 256;       // 0..2047
            int r = idx >> 5, c = (idx & 31) * 8;
            CP16(saddr(Asm + st * TILE_E + r * TSTRIDE + c), X  + (size_t)(row0 + r) * K + kbase + c);
            CP16(saddr(Bsm + st * TILE_E + r * TSTRIDE + c), Wt + (size_t)(col0 + r) * K + kbase + c);
        }
        CP_COMMIT();
    };

    // prologue
    fill(0, 0);
    if (ST == 2) fill(1, 1);

    for (int ph = 0; ph < PH; ph++) {
        if (ST == 2 && ph + 1 < PH) { CP_WAIT1(); } else { CP_WAIT0(); }
        __syncthreads();
        int st = ph % ST;
        uint32_t ab = saddr(Asm + st * TILE_E) + 2 * (wm * 16 * TSTRIDE + laneA);
        uint32_t bb = saddr(Bsm + st * TILE_E) + 2 * (wn * 32 * TSTRIDE + laneB);
        #pragma unroll
        for (int ks = 0; ks < 16; ks++) {
            uint32_t a0, a1, a2, a3, b0, b1, b2, b3, c0, c1, c2, c3;
            ldsm4(a0, a1, a2, a3, ab + 2 * (ks * 16));
            ldsm4(b0, b1, b2, b3, bb + 2 * (ks * 16));
            ldsm4(c0, c1, c2, c3, bb + 2 * (16 * TSTRIDE + ks * 16));
            mma_bf16(acc[0], a0, a1, a2, a3, b0, b1);
            mma_bf16(acc[1], a0, a1, a2, a3, b2, b3);
            mma_bf16(acc[2], a0, a1, a2, a3, c0, c1);
            mma_bf16(acc[3], a0, a1, a2, a3, c2, c3);
        }
        if (ph + ST < PH) {
            __syncthreads();               // everyone done reading stage st
            fill(st, ph + ST);
        } else {
            CP_COMMIT();                   // keep group counts consistent
        }
    }

    #pragma unroll
    for (int nj = 0; nj < 4; nj++) {
        int r = row0 + wm * 16 + rg;
        int c = col0 + wn * 32 + nj * 8 + qd * 2;
        void* Yp = Yv;
        const float* bp = bias;
        int cc = c;
        if (DUAL && c >= NOUT) { Yp = Yv2; bp = bias2; cc = c - NOUT; }
        float b0v = bp ? bp[cc] : 0.f;
        float b1v = bp ? bp[cc + 1] : 0.f;
        #pragma unroll
        for (int half = 0; half < 2; half++) {
            int rr = r + half * 8;
            float z0 = acc[nj][half * 2 + 0] + b0v;
            float z1 = acc[nj][half * 2 + 1] + b1v;
            if (EPI == 1) {
                z0 = (z0 > 0.f) ? (z0 + 1.f) : __expf(z0);
                z1 = (z1 > 0.f) ? (z1 + 1.f) : __expf(z1);
            } else if (EPI == 2) {
                const float2 rv = *(const float2*)&res[(size_t)rr * NOUT + cc];
                z0 += rv.x; z1 += rv.y;
            }
            size_t off = (size_t)rr * NOUT + cc;
            if (OUTBF) {
                *(__nv_bfloat162*)((__nv_bfloat16*)Yp + off) =
                    __float22bfloat162_rn(make_float2(z0, z1));
            } else {
                *(float2*)((float*)Yp + off) = make_float2(z0, z1);
            }
        }
    }
}

// ---------------- linear-attn KV/Ksum partials ----------------
__global__ void kv_accum()
{
    int nh = blockIdx.x, part = blockIdx.y;
    int n = nh >> 3, h = nh & 7;
    int tid = threadIdx.x;          // 1024
    int d = tid >> 5, vv = tid & 31;
    __shared__ float sk[64][32], sv[64][32];
    float acc = 0.f, ks = 0.f;
    int base = part * 256;
    for (int c0 = base; c0 < base + 256; c0 += 64) {
        __syncthreads();
        #pragma unroll
        for (int it = 0; it < 2; it++) {
            int idx = tid + it * 1024;
            int s = idx >> 5, dd = idx & 31;
            size_t gbase = (size_t)(n * LQ + c0 + s) * CH + h * DH + dd;
            sk[s][dd] = g_k[gbase];
            sv[s][dd] = g_v[gbase];
        }
        __syncthreads();
        #pragma unroll
        for (int s = 0; s < 64; s++) {
            float kd = sk[s][d];
            acc += kd * sv[s][vv];
            ks  += kd;
        }
    }
    g_kvp[(size_t)((nh << 3) + part) * (DH*DH) + d * DH + vv] = acc;
    if (vv == 0) g_ksp[((nh << 3) + part) * DH + d] = ks;
}

__global__ void kv_reduce()
{
    int nh = blockIdx.x, i = threadIdx.x;
    float s = 0.f;
    #pragma unroll
    for (int p = 0; p < 8; p++) s += g_kvp[(size_t)((nh << 3) + p) * (DH*DH) + i];
    g_kv[(size_t)nh * (DH*DH) + i] = s;
    if (i < DH) {
        float ks = 0.f;
        #pragma unroll
        for (int p = 0; p < 8; p++) ks += g_ksp[((nh << 3) + p) * DH + i];
        g_ksum[nh * DH + i] = ks;
    }
}

// ---------------- linear-attn output (bf16 out) ----------------
__global__ void lin_out()
{
    int row = blockIdx.x;
    int n = row >> 11;
    int tid = threadIdx.x;
    int h = tid >> 5, lane = tid & 31;
    __shared__ float qsh[CH];
    qsh[tid] = g_q[(size_t)row * CH + tid];
    __syncthreads();
    int nh = n * NH + h;
    float z = qsh[h * DH + lane] * g_ksum[nh * DH + lane];
    #pragma unroll
    for (int off = 16; off > 0; off >>= 1) z += __shfl_xor_sync(0xffffffffu, z, off);
    float zinv = 1.f / (z + 1e-6f);
    const float* kvp = g_kv + (size_t)nh * (DH*DH);
    float acc = 0.f;
    #pragma unroll
    for (int dd = 0; dd < DH; dd++) acc += qsh[h * DH + dd] * kvp[dd * DH + lane];
    g_laob[(size_t)row * CH + tid] = __float2bfloat16(acc * zinv);
}

// ---------------- mem = bf16(memory + pos_embed) ----------------
__global__ void mem_add(const float* __restrict__ memory, const float* __restrict__ pos)
{
    int i4 = blockIdx.x * blockDim.x + threadIdx.x;
    const int PER_N = SK * CH / 4;
    int p4 = i4 % PER_N;
    float4 a = ((const float4*)memory)[i4];
    float4 b = ((const float4*)pos)[p4];
    uint32_t lo = pack_bf16(a.x + b.x, a.y + b.y);
    uint32_t hi = pack_bf16(a.z + b.z, a.w + b.w);
    ((uint2*)g_memb)[i4] = make_uint2(lo, hi);
}

// ---------------- V transpose per (n,h): [s][d] -> [d][s] ----------------
__global__ void vtrans()
{
    __shared__ __nv_bfloat16 t[32][33];
    int s0 = blockIdx.x * 32;
    int nh = blockIdx.y;
    int n = nh >> 3, h = nh & 7;
    int tx = threadIdx.x, ty = threadIdx.y;   // (32,8)
    #pragma unroll
    for (int i = 0; i < 4; i++)
        t[ty + i * 8][tx] = g_cvb[(size_t)(n * SK + s0 + ty + i * 8) * CH + h * DH + tx];
    __syncthreads();
    #pragma unroll
    for (int i = 0; i < 4; i++)
        g_cvt[(size_t)(nh * DH + ty + i * 8) * SK + s0 + tx] = t[tx][ty + i * 8];
}

// ---------------- flash attention: 128q x 64s tiles, 8 warps, 3-stage, ldmatrix ----------------
__global__ void flash_attn_mma()
{
    __shared__ __nv_bfloat16 Qs[128][36];
    __shared__ __nv_bfloat16 Ks[3][64][40];
    __shared__ __nv_bfloat16 Vs[3][32][72];
    int tid = threadIdx.x;               // 256
    int lane = tid & 31, wid = tid >> 5;
    int qd = lane & 3, rg = lane >> 2;
    int qb = blockIdx.x * 128, h = blockIdx.y, n = blockIdx.z;
    int nh = n * NH + h;
    const float scale = 0.17677669529663687f;   // 32^-0.5

    #pragma unroll
    for (int i = 0; i < 8; i++) {
        int idx = tid + i * 256;
        int r = idx >> 4, dp = idx & 15;
        uint32_t v = *(const uint32_t*)&g_cqb[(size_t)(n * LQ + qb + r) * CH + h * DH + dp * 2];
        *(uint32_t*)&Qs[r][dp * 2] = v;
    }

    int kr = tid >> 2, kc = (tid & 3) * 8;
    int vr = tid >> 3, vc = (tid & 7) * 8;
    const int T = SK / 64;
    #pragma unroll
    for (int pt = 0; pt < 2; pt++) {
        int sb = pt * 64;
        CP16(saddr(&Ks[pt][kr][kc]), g_ckb + (size_t)(n * SK + sb + kr) * CH + h * DH + kc);
        CP16(saddr(&Vs[pt][vr][vc]), g_cvt + (size_t)(nh * DH + vr) * SK + sb + vc);
        CP_COMMIT();
    }
    __syncthreads();   // Qs visible

    int r0 = wid * 16 + rg;
    uint32_t aq[2][4];
    #pragma unroll
    for (int ks = 0; ks < 2; ks++) {
        aq[ks][0] = *(uint32_t*)&Qs[r0    ][ks * 16 + qd * 2];
        aq[ks][1] = *(uint32_t*)&Qs[r0 + 8][ks * 16 + qd * 2];
        aq[ks][2] = *(uint32_t*)&Qs[r0    ][ks * 16 + qd * 2 + 8];
        aq[ks][3] = *(uint32_t*)&Qs[r0 + 8][ks * 16 + qd * 2 + 8];
    }

    int laneK = ((lane & 7) + (lane >> 4) * 8) * 40 + ((lane >> 3) & 1) * 8;
    int laneV = ((lane & 7) + (lane >> 4) * 8) * 72 + ((lane >> 3) & 1) * 8;

    float m0 = -1e30f, m1 = -1e30f, l0 = 0.f, l1 = 0.f;
    float o[4][4] = {};

    for (int kt = 0; kt < T; kt++) {
        CP_WAIT1();
        __syncthreads();
        int st = kt % 3;

        float sc[8][4];
        #pragma unroll
        for (int j = 0; j < 8; j++)
            #pragma unroll
            for (int e = 0; e < 4; e++) sc[j][e] = 0.f;
        uint32_t kb = saddr(&Ks[st][0][0]) + 2 * laneK;
        #pragma unroll
        for (int ks = 0; ks < 2; ks++) {
            #pragma unroll
            for (int jj = 0; jj < 4; jj++) {
                uint32_t b0, b1, b2, b3;
                ldsm4(b0, b1, b2, b3, kb + 2 * (jj * 16 * 40 + ks * 16));
                mma_bf16(sc[2 * jj    ], aq[ks][0], aq[ks][1], aq[ks][2], aq[ks][3], b0, b1);
                mma_bf16(sc[2 * jj + 1], aq[ks][0], aq[ks][1], aq[ks][2], aq[ks][3], b2, b3);
            }
        }

        float rm0 = -1e30f, rm1 = -1e30f;
        #pragma unroll
        for (int j = 0; j < 8; j++) {
            rm0 = fmaxf(rm0, fmaxf(sc[j][0], sc[j][1]));
            rm1 = fmaxf(rm1, fmaxf(sc[j][2], sc[j][3]));
        }
        rm0 = fmaxf(rm0, __shfl_xor_sync(0xffffffffu, rm0, 1));
        rm0 = fmaxf(rm0, __shfl_xor_sync(0xffffffffu, rm0, 2));
        rm1 = fmaxf(rm1, __shfl_xor_sync(0xffffffffu, rm1, 1));
        rm1 = fmaxf(rm1, __shfl_xor_sync(0xffffffffu, rm1, 2));
        float mn0 = fmaxf(m0, rm0), mn1 = fmaxf(m1, rm1);
        float corr0 = __expf((m0 - mn0) * scale);
        float corr1 = __expf((m1 - mn1) * scale);
        float s0 = 0.f, s1 = 0.f;
        #pragma unroll
        for (int j = 0; j < 8; j++) {
            sc[j][0] = __expf((sc[j][0] - mn0) * scale);
            sc[j][1] = __expf((sc[j][1] - mn0) * scale);
            sc[j][2] = __expf((sc[j][2] - mn1) * scale);
            sc[j][3] = __expf((sc[j][3] - mn1) * scale);
            s0 += sc[j][0] + sc[j][1];
            s1 += sc[j][2] + sc[j][3];
        }
        s0 += __shfl_xor_sync(0xffffffffu, s0, 1);
        s0 += __shfl_xor_sync(0xffffffffu, s0, 2);
        s1 += __shfl_xor_sync(0xffffffffu, s1, 1);
        s1 += __shfl_xor_sync(0xffffffffu, s1, 2);
        l0 = l0 * corr0 + s0;
        l1 = l1 * corr1 + s1;
        m0 = mn0; m1 = mn1;
        #pragma unroll
        for (int dj = 0; dj < 4; dj++) {
            o[dj][0] *= corr0; o[dj][1] *= corr0;
            o[dj][2] *= corr1; o[dj][3] *= corr1;
        }

        uint32_t vb = saddr(&Vs[st][0][0]) + 2 * laneV;
        #pragma unroll
        for (int t = 0; t < 4; t++) {
            uint32_t pa0 = pack_bf16(sc[2 * t    ][0], sc[2 * t    ][1]);
            uint32_t pa1 = pack_bf16(sc[2 * t    ][2], sc[2 * t    ][3]);
            uint32_t pa2 = pack_bf16(sc[2 * t + 1][0], sc[2 * t + 1][1]);
            uint32_t pa3 = pack_bf16(sc[2 * t + 1][2], sc[2 * t + 1][3]);
            #pragma unroll
            for (int dd = 0; dd < 2; dd++) {
                uint32_t v0, v1, v2, v3;
                ldsm4(v0, v1, v2, v3, vb + 2 * (dd * 16 * 72 + t * 16));
                mma_bf16(o[2 * dd    ], pa0, pa1, pa2, pa3, v0, v1);
                mma_bf16(o[2 * dd + 1], pa0, pa1, pa2, pa3, v2, v3);
            }
        }

        if (kt + 2 < T) {
            int st2 = (kt + 2) % 3, sb = (kt + 2) * 64;
            CP16(saddr(&Ks[st2][kr][kc]), g_ckb + (size_t)(n * SK + sb + kr) * CH + h * DH + kc);
            CP16(saddr(&Vs[st2][vr][vc]), g_cvt + (size_t)(nh * DH + vr) * SK + sb + vc);
        }
        CP_COMMIT();
    }

    float inv0 = 1.f / l0, inv1 = 1.f / l1;
    #pragma unroll
    for (int dj = 0; dj < 4; dj++) {
        size_t b0 = (size_t)(n * LQ + qb + r0    ) * CH + h * DH + dj * 8 + qd * 2;
        size_t b1 = (size_t)(n * LQ + qb + r0 + 8) * CH + h * DH + dj * 8 + qd * 2;
        *(__nv_bfloat162*)&g_cob[b0] = __float22bfloat162_rn(make_float2(o[dj][0] * inv0, o[dj][1] * inv0));
        *(__nv_bfloat162*)&g_cob[b1] = __float22bfloat162_rn(make_float2(o[dj][2] * inv1, o[dj][3] * inv1));
    }
}

// ---------------- depthwise conv3 (along L) + bias + exact gelu (bf16 in/out) ----------------
__global__ void conv_gelu(const float* __restrict__ dwk, const float* __restrict__ dwb)
{
    int i = blockIdx.x * blockDim.x + threadIdx.x;
    int c = i & (HID - 1);
    int l = (i >> 10) & (LQ - 1);
    float k0 = dwk[c * 9 + 1];
    float k1 = dwk[c * 9 + 4];
    float k2 = dwk[c * 9 + 7];
    float v = __bfloat162float(g_hb[i]) * k1;
    if (l > 0)      v += __bfloat162float(g_hb[i - HID]) * k0;
    if (l < LQ - 1) v += __bfloat162float(g_hb[i + HID]) * k2;
    v += dwb[c];
    float out = 0.5f * v * (1.f + erff(v * 0.70710678118654752f));
    g_h2b[i] = __float2bfloat16(out);
}

// ---------------- host ----------------
extern "C" void kernel_launch(void* const* d_in, const int* in_sizes, int n_in,
                              void* d_out, int out_size)
{
    const float* tgt      = (const float*)d_in[0];
    const float* memory   = (const float*)d_in[1];
    const float* tgt_pos  = (const float*)d_in[2];
    const float* pos_emb  = (const float*)d_in[3];
    const float* ln1_g = (const float*)d_in[4],  *ln1_b = (const float*)d_in[5];
    const float* ln2_g = (const float*)d_in[6],  *ln2_b = (const float*)d_in[7];
    const float* ln3_g = (const float*)d_in[8],  *ln3_b = (const float*)d_in[9];
    const float* wq = (const float*)d_in[10], *bq = (const float*)d_in[11];
    const float* wk = (const float*)d_in[12], *bk = (const float*)d_in[13];
    const float* wv = (const float*)d_in[14], *bv = (const float*)d_in[15];
    const float* w_merge = (const float*)d_in[16];
    const float* cwq = (const float*)d_in[17], *cbq = (const float*)d_in[18];
    const float* cwk = (const float*)d_in[19], *cbk = (const float*)d_in[20];
    const float* cwv = (const float*)d_in[21], *cbv = (const float*)d_in[22];
    const float* cwo = (const float*)d_in[23], *cbo = (const float*)d_in[24];
    const float* mw1 = (const float*)d_in[25], *mb1 = (const float*)d_in[26];
    const float* dwk = (const float*)d_in[27], *dwb = (const float*)d_in[28];
    const float* mw2 = (const float*)d_in[29], *mb2 = (const float*)d_in[30];
    float* out = (float*)d_out;

    float *p_q, *p_k, *p_v, *p_t1, *p_t2;
    __nv_bfloat16 *p_xb1, *p_xb2, *p_laob, *p_memb, *p_cqb, *p_ckb, *p_cvb, *p_cob, *p_hb, *p_h2b, *p_wts;
    cudaGetSymbolAddress((void**)&p_q,    g_q);
    cudaGetSymbolAddress((void**)&p_k,    g_k);
    cudaGetSymbolAddress((void**)&p_v,    g_v);
    cudaGetSymbolAddress((void**)&p_t1,   g_t1);
    cudaGetSymbolAddress((void**)&p_t2,   g_t2);
    cudaGetSymbolAddress((void**)&p_xb1,  g_xb1);
    cudaGetSymbolAddress((void**)&p_xb2,  g_xb2);
    cudaGetSymbolAddress((void**)&p_laob, g_laob);
    cudaGetSymbolAddress((void**)&p_memb, g_memb);
    cudaGetSymbolAddress((void**)&p_cqb,  g_cqb);
    cudaGetSymbolAddress((void**)&p_ckb,  g_ckb);
    cudaGetSymbolAddress((void**)&p_cvb,  g_cvb);
    cudaGetSymbolAddress((void**)&p_cob,  g_cob);
    cudaGetSymbolAddress((void**)&p_hb,   g_hb);
    cudaGetSymbolAddress((void**)&p_h2b,  g_h2b);
    cudaGetSymbolAddress((void**)&p_wts,  g_wts);

    // dynamic smem: 1 stage = 2 tiles * 64*264*2 B = 67584; 2 stages = 135168
    const int SM1 = 2 * TILE_E * 2;
    const int SM2 = 2 * SM1;
    cudaFuncSetAttribute(gemm_v3<1, false, true>,  cudaFuncAttributeMaxDynamicSharedMemorySize, SM2);
    cudaFuncSetAttribute(gemm_v3<0, false, false>, cudaFuncAttributeMaxDynamicSharedMemorySize, SM2);
    cudaFuncSetAttribute(gemm_v3<2, false, false>, cudaFuncAttributeMaxDynamicSharedMemorySize, SM2);
    cudaFuncSetAttribute(gemm_v3<0, true, false>,  cudaFuncAttributeMaxDynamicSharedMemorySize, SM2);
    cudaFuncSetAttribute(gemm_v3<0, true, true>,   cudaFuncAttributeMaxDynamicSharedMemorySize, SM2);

    // ---- fused weight transpose (1 launch) ----
    WSrc ws;
    ws.p[0] = wq;  ws.p[1] = wk;  ws.p[2] = wv;  ws.p[3] = w_merge;
    ws.p[4] = cwq; ws.p[5] = cwk; ws.p[6] = cwv; ws.p[7] = cwo;
    ws.p[8] = mw1; ws.p[9] = mw2;
    wtrans_all<<<1024, dim3(32, 8)>>>(ws, p_wts);

    dim3 gq(CH / 64, NLROWS / 64);         // (4,128)
    dim3 gdual(2 * CH / 64, NLROWS / 64);  // (8,128)
    dim3 gmemd(2 * CH / 64, NSROWS / 64);  // (8,256)
    dim3 gm1(HID / 64, NLROWS / 64);       // (16,128)

    // ---- self attention (linear attention) ----
    ln_kernel<<<NLROWS, 256>>>(tgt, ln1_g, ln1_b, tgt_pos, p_xb1, p_xb2);
    gemm_v3<1, false, true><<<gdual, 256, SM1>>>(p_xb2, p_wts + WT_WQ, bq, bk, nullptr,
                                                 p_q, p_k, NLROWS, CH, CH);
    gemm_v3<0, false, false><<<gq, 256, SM1>>>(p_xb1, p_wts + WT_WV, bv, nullptr, nullptr,
                                               p_v, nullptr, NLROWS, CH, CH);
    kv_accum<<<dim3(NB * NH, 8), 1024>>>();
    kv_reduce<<<NB * NH, 1024>>>();
    lin_out<<<NLROWS, 256>>>();
    gemm_v3<2, false, false><<<gq, 256, SM1>>>(p_laob, p_wts + WT_WM, nullptr, nullptr, tgt,
                                               p_t1, nullptr, NLROWS, CH, CH);

    // ---- cross attention ----
    ln_kernel<<<NLROWS, 256>>>(p_t1, ln2_g, ln2_b, nullptr, p_xb1, nullptr);
    mem_add<<<NSROWS * CH / 4 / 256, 256>>>(memory, pos_emb);
    gemm_v3<0, true, false><<<gq, 256, SM1>>>(p_xb1, p_wts + WT_CWQ, cbq, nullptr, nullptr,
                                              p_cqb, nullptr, NLROWS, CH, CH);
    gemm_v3<0, true, true><<<gmemd, 256, SM1>>>(p_memb, p_wts + WT_CWK, cbk, cbv, nullptr,
                                                p_ckb, p_cvb, NSROWS, CH, CH);
    vtrans<<<dim3(SK / 32, NB * NH), dim3(32, 8)>>>();
    flash_attn_mma<<<dim3(LQ / 128, NH, NB), 256>>>();
    gemm_v3<2, false, false><<<gq, 256, SM1>>>(p_cob, p_wts + WT_CWO, cbo, nullptr, p_t1,
                                               p_t2, nullptr, NLROWS, CH, CH);

    // ---- MLP ----
    ln_kernel<<<NLROWS, 256>>>(p_t2, ln3_g, ln3_b, nullptr, p_xb1, nullptr);
    gemm_v3<0, true, false><<<gm1, 256, SM1>>>(p_xb1, p_wts + WT_MW1, mb1, nullptr, nullptr,
                                               p_hb, nullptr, NLROWS, CH, HID);
    conv_gelu<<<NLROWS * HID / 256, 256>>>(dwk, dwb);
    gemm_v3<2, false, false><<<gq, 256, SM2>>>(p_h2b, p_wts + WT_MW2, mb2, nullptr, p_t2,
                                               out, nullptr, NLROWS, HID, CH);
}

// round 10
// speedup vs baseline: 1.0345x; 1.0345x over previous
#include <cuda_runtime.h>
#include <cuda_bf16.h>
#include <math.h>
#include <stdint.h>

#define NB 4
#define LQ 2048
#define SK 4096
#define CH 256
#define NH 8
#define DH 32
#define HID 1024
#define NLROWS (NB*LQ)      // 8192
#define NSROWS (NB*SK)      // 16384

// ---------------- scratch (device globals; no runtime alloc) ----------------
__device__ float g_q   [NLROWS*CH];
__device__ float g_k   [NLROWS*CH];
__device__ float g_v   [NLROWS*CH];
__device__ float g_t1  [NLROWS*CH];
__device__ float g_t2  [NLROWS*CH];
__device__ float g_kv  [NB*NH*DH*DH];
__device__ float g_ksum[NB*NH*DH];
__device__ float g_kvp [NB*NH*8*DH*DH];
__device__ float g_ksp [NB*NH*8*DH];

__device__ __nv_bfloat16 g_xb1 [NLROWS*CH];
__device__ __nv_bfloat16 g_xb2 [NLROWS*CH];
__device__ __nv_bfloat16 g_laob[NLROWS*CH];
__device__ __nv_bfloat16 g_memb[NSROWS*CH];
__device__ __nv_bfloat16 g_cqb [NLROWS*CH];
__device__ __nv_bfloat16 g_ckb [NSROWS*CH];
__device__ __nv_bfloat16 g_cvb [NSROWS*CH];
__device__ __nv_bfloat16 g_cvt [NB*NH*DH*SK];
__device__ __nv_bfloat16 g_cob [NLROWS*CH];
__device__ __nv_bfloat16 g_hb  [NLROWS*HID];
__device__ __nv_bfloat16 g_h2b [NLROWS*HID];
__device__ __nv_bfloat16 g_wts [8*CH*CH + CH*HID + HID*CH];

#define WT_WQ   0
#define WT_WK   (1*CH*CH)
#define WT_WV   (2*CH*CH)
#define WT_WM   (3*CH*CH)
#define WT_CWQ  (4*CH*CH)
#define WT_CWK  (5*CH*CH)
#define WT_CWV  (6*CH*CH)
#define WT_CWO  (7*CH*CH)
#define WT_MW1  (8*CH*CH)
#define WT_MW2  (8*CH*CH + CH*HID)

// ---------------- helpers ----------------
__device__ __forceinline__ void mma_bf16(float* c, uint32_t a0, uint32_t a1, uint32_t a2, uint32_t a3,
                                         uint32_t b0, uint32_t b1)
{
    asm volatile("mma.sync.aligned.m16n8k16.row.col.f32.bf16.bf16.f32 "
                 "{%0,%1,%2,%3}, {%4,%5,%6,%7}, {%8,%9}, {%0,%1,%2,%3};"
                 : "+f"(c[0]), "+f"(c[1]), "+f"(c[2]), "+f"(c[3])
                 : "r"(a0), "r"(a1), "r"(a2), "r"(a3), "r"(b0), "r"(b1));
}

__device__ __forceinline__ void ldsm4(uint32_t& r0, uint32_t& r1, uint32_t& r2, uint32_t& r3, uint32_t a)
{
    asm volatile("ldmatrix.sync.aligned.m8n8.x4.shared.b16 {%0,%1,%2,%3}, [%4];"
                 : "=r"(r0), "=r"(r1), "=r"(r2), "=r"(r3) : "r"(a));
}

__device__ __forceinline__ uint32_t pack_bf16(float lo, float hi)
{
    __nv_bfloat162 t = __float22bfloat162_rn(make_float2(lo, hi));
    return *(uint32_t*)&t;
}

__device__ __forceinline__ uint32_t saddr(const void* p)
{
    return (uint32_t)__cvta_generic_to_shared(p);
}

#define CP16(dst, src) asm volatile("cp.async.cg.shared.global [%0], [%1], 16;" :: "r"(dst), "l"(src))
#define CP_COMMIT()    asm volatile("cp.async.commit_group;")
#define CP_WAIT0()     asm volatile("cp.async.wait_group 0;")
#define CP_WAIT1()     asm volatile("cp.async.wait_group 1;")

// ---------------- fused weight transpose: all 10 weights in one launch ----------------
struct WSrc { const float* p[10]; };

__global__ void wtrans_all(WSrc ws, __nv_bfloat16* __restrict__ dst)
{
    __shared__ float t[32][33];
    int bid = blockIdx.x;
    int w, kt, nt;
    if (bid < 512)       { w = bid >> 6;  int r = bid & 63;   kt = r >> 3; nt = r & 7;  }
    else if (bid < 768)  { w = 8;         int r = bid - 512;  kt = r >> 5; nt = r & 31; }
    else                 { w = 9;         int r = bid - 768;  kt = r >> 3; nt = r & 7;  }
    int Kd = (w == 9) ? 1024 : 256;
    int Nd = (w == 8) ? 1024 : 256;
    size_t doff = (w < 8) ? (size_t)w * (CH*CH) : (w == 8 ? (size_t)8*CH*CH : (size_t)8*CH*CH + CH*HID);
    const float* W = ws.p[w];
    __nv_bfloat16* Wt = dst + doff;
    int n0 = nt * 32, k0 = kt * 32;
    int tx = threadIdx.x, ty = threadIdx.y;   // (32,8)
    #pragma unroll
    for (int i = 0; i < 4; i++)
        t[ty + i * 8][tx] = W[(size_t)(k0 + ty + i * 8) * Nd + n0 + tx];
    __syncthreads();
    #pragma unroll
    for (int i = 0; i < 4; i++)
        Wt[(size_t)(n0 + ty + i * 8) * Kd + k0 + tx] = __float2bfloat16(t[tx][ty + i * 8]);
}

// ---------------- LayerNorm: bf16 outputs (y, optional y2=y+addp) ----------------
__global__ void ln_kernel(const float* __restrict__ x, const float* __restrict__ g,
                          const float* __restrict__ b, const float* __restrict__ addp,
                          __nv_bfloat16* __restrict__ y, __nv_bfloat16* __restrict__ y2)
{
    int row = blockIdx.x, tid = threadIdx.x;
    size_t base = (size_t)row * CH;
    float v = x[base + tid];
    float s1 = v, s2 = v * v;
    #pragma unroll
    for (int off = 16; off > 0; off >>= 1) {
        s1 += __shfl_xor_sync(0xffffffffu, s1, off);
        s2 += __shfl_xor_sync(0xffffffffu, s2, off);
    }
    __shared__ float r1[8], r2[8];
    int warp = tid >> 5, lane = tid & 31;
    if (lane == 0) { r1[warp] = s1; r2[warp] = s2; }
    __syncthreads();
    float t1 = 0.f, t2 = 0.f;
    #pragma unroll
    for (int w = 0; w < 8; w++) { t1 += r1[w]; t2 += r2[w]; }
    float mean = t1 * (1.f / CH);
    float var  = t2 * (1.f / CH) - mean * mean;
    float inv  = rsqrtf(var + 1e-5f);
    float out  = (v - mean) * inv * g[tid] + b[tid];
    y[base + tid] = __float2bfloat16(out);
    if (y2) y2[base + tid] = __float2bfloat16(out + addp[base + tid]);
}

// ---------------- bf16 GEMM v4: BM=128, BN=128, KC=128 double-buffer ----------------
// 256 threads (8 warps: 4m x 2n, warp tile 32x64). Minimizes cp.async op count
// (the measured chip-wide bottleneck: ~8cyc per 16B op per SMSP).
// EPI 0: +bias ; EPI 1: elu(z)+1 ; EPI 2: +bias +res.  OUTBF: write bf16.
#define TS4 136                          // row stride (elems); 272B: ldmatrix conflict-free
#define TILE4 (128 * TS4)                // elems per tile (one stage, one operand)

template<int EPI, bool OUTBF, bool DUAL>
__global__ void __launch_bounds__(256)
gemm_v4(const __nv_bfloat16* __restrict__ X, const __nv_bfloat16* __restrict__ Wt,
        const float* __restrict__ bias, const float* __restrict__ bias2,
        const float* __restrict__ res,
        void* __restrict__ Yv, void* __restrict__ Yv2,
        int M, int K, int NOUT)
{
    extern __shared__ __nv_bfloat16 sm[];
    __nv_bfloat16* Asm = sm;              // [2][128][TS4]
    __nv_bfloat16* Bsm = sm + 2 * TILE4;  // [2][128][TS4]
    const int PH = K / 128;               // >= 2 for all our K

    int tid = threadIdx.x;
    int lane = tid & 31, wid = tid >> 5;
    int qd = lane & 3, rg = lane >> 2;
    int wm = wid >> 1, wn = wid & 1;
    int row0 = blockIdx.y * 128, col0 = blockIdx.x * 128;

    float acc[2][8][4];
    #pragma unroll
    for (int mi = 0; mi < 2; mi++)
        #pragma unroll
        for (int nj = 0; nj < 8; nj++)
            #pragma unroll
            for (int e = 0; e < 4; e++) acc[mi][nj][e] = 0.f;

    int laneA = ((lane & 7) + ((lane >> 3) & 1) * 8) * TS4 + (lane >> 4) * 8;
    int laneB = ((lane & 7) + (lane >> 4) * 8) * TS4 + ((lane >> 3) & 1) * 8;

    auto fill = [&](int st, int ph) {
        int kbase = ph * 128;
        #pragma unroll
        for (int j = 0; j < 8; j++) {
            int idx = tid + j * 256;           // 0..2047
            int r = idx >> 4, c = (idx & 15) * 8;
            CP16(saddr(Asm + st * TILE4 + r * TS4 + c), X  + (size_t)(row0 + r) * K + kbase + c);
            CP16(saddr(Bsm + st * TILE4 + r * TS4 + c), Wt + (size_t)(col0 + r) * K + kbase + c);
        }
        CP_COMMIT();
    };

    fill(0, 0);
    fill(1, 1);

    for (int ph = 0; ph < PH; ph++) {
        if (ph + 1 < PH) { CP_WAIT1(); } else { CP_WAIT0(); }
        __syncthreads();
        int st = ph & 1;
        uint32_t ab = saddr(Asm + st * TILE4) + 2 * (wm * 32 * TS4 + laneA);
        uint32_t bb = saddr(Bsm + st * TILE4) + 2 * (wn * 64 * TS4 + laneB);
        #pragma unroll
        for (int ks = 0; ks < 8; ks++) {
            uint32_t a0[4], a1[4];
            ldsm4(a0[0], a0[1], a0[2], a0[3], ab + 2 * (ks * 16));
            ldsm4(a1[0], a1[1], a1[2], a1[3], ab + 2 * (16 * TS4 + ks * 16));
            #pragma unroll
            for (int nn = 0; nn < 4; nn++) {
                uint32_t b0, b1, b2, b3;
                ldsm4(b0, b1, b2, b3, bb + 2 * (nn * 16 * TS4 + ks * 16));
                mma_bf16(acc[0][2 * nn    ], a0[0], a0[1], a0[2], a0[3], b0, b1);
                mma_bf16(acc[0][2 * nn + 1], a0[0], a0[1], a0[2], a0[3], b2, b3);
                mma_bf16(acc[1][2 * nn    ], a1[0], a1[1], a1[2], a1[3], b0, b1);
                mma_bf16(acc[1][2 * nn + 1], a1[0], a1[1], a1[2], a1[3], b2, b3);
            }
        }
        if (ph + 2 < PH) {
            __syncthreads();                   // all warps done reading stage st
            fill(st, ph + 2);
        } else {
            CP_COMMIT();                       // keep group counts consistent
        }
    }

    #pragma unroll
    for (int mi = 0; mi < 2; mi++) {
        #pragma unroll
        for (int nj = 0; nj < 8; nj++) {
            int r = row0 + wm * 32 + mi * 16 + rg;
            int c = col0 + wn * 64 + nj * 8 + qd * 2;
            void* Yp = Yv;
            const float* bp = bias;
            int cc = c;
            if (DUAL && c >= NOUT) { Yp = Yv2; bp = bias2; cc = c - NOUT; }
            float b0v = bp ? bp[cc] : 0.f;
            float b1v = bp ? bp[cc + 1] : 0.f;
            #pragma unroll
            for (int half = 0; half < 2; half++) {
                int rr = r + half * 8;
                float z0 = acc[mi][nj][half * 2 + 0] + b0v;
                float z1 = acc[mi][nj][half * 2 + 1] + b1v;
                if (EPI == 1) {
                    z0 = (z0 > 0.f) ? (z0 + 1.f) : __expf(z0);
                    z1 = (z1 > 0.f) ? (z1 + 1.f) : __expf(z1);
                } else if (EPI == 2) {
                    const float2 rv = *(const float2*)&res[(size_t)rr * NOUT + cc];
                    z0 += rv.x; z1 += rv.y;
                }
                size_t off = (size_t)rr * NOUT + cc;
                if (OUTBF) {
                    *(__nv_bfloat162*)((__nv_bfloat16*)Yp + off) =
                        __float22bfloat162_rn(make_float2(z0, z1));
                } else {
                    *(float2*)((float*)Yp + off) = make_float2(z0, z1);
                }
            }
        }
    }
}

// ---------------- linear-attn KV/Ksum partials ----------------
__global__ void kv_accum()
{
    int nh = blockIdx.x, part = blockIdx.y;
    int n = nh >> 3, h = nh & 7;
    int tid = threadIdx.x;          // 1024
    int d = tid >> 5, vv = tid & 31;
    __shared__ float sk[64][32], sv[64][32];
    float acc = 0.f, ks = 0.f;
    int base = part * 256;
    for (int c0 = base; c0 < base + 256; c0 += 64) {
        __syncthreads();
        #pragma unroll
        for (int it = 0; it < 2; it++) {
            int idx = tid + it * 1024;
            int s = idx >> 5, dd = idx & 31;
            size_t gbase = (size_t)(n * LQ + c0 + s) * CH + h * DH + dd;
            sk[s][dd] = g_k[gbase];
            sv[s][dd] = g_v[gbase];
        }
        __syncthreads();
        #pragma unroll
        for (int s = 0; s < 64; s++) {
            float kd = sk[s][d];
            acc += kd * sv[s][vv];
            ks  += kd;
        }
    }
    g_kvp[(size_t)((nh << 3) + part) * (DH*DH) + d * DH + vv] = acc;
    if (vv == 0) g_ksp[((nh << 3) + part) * DH + d] = ks;
}

__global__ void kv_reduce()
{
    int nh = blockIdx.x, i = threadIdx.x;
    float s = 0.f;
    #pragma unroll
    for (int p = 0; p < 8; p++) s += g_kvp[(size_t)((nh << 3) + p) * (DH*DH) + i];
    g_kv[(size_t)nh * (DH*DH) + i] = s;
    if (i < DH) {
        float ks = 0.f;
        #pragma unroll
        for (int p = 0; p < 8; p++) ks += g_ksp[((nh << 3) + p) * DH + i];
        g_ksum[nh * DH + i] = ks;
    }
}

// ---------------- linear-attn output (bf16 out) ----------------
__global__ void lin_out()
{
    int row = blockIdx.x;
    int n = row >> 11;
    int tid = threadIdx.x;
    int h = tid >> 5, lane = tid & 31;
    __shared__ float qsh[CH];
    qsh[tid] = g_q[(size_t)row * CH + tid];
    __syncthreads();
    int nh = n * NH + h;
    float z = qsh[h * DH + lane] * g_ksum[nh * DH + lane];
    #pragma unroll
    for (int off = 16; off > 0; off >>= 1) z += __shfl_xor_sync(0xffffffffu, z, off);
    float zinv = 1.f / (z + 1e-6f);
    const float* kvp = g_kv + (size_t)nh * (DH*DH);
    float acc = 0.f;
    #pragma unroll
    for (int dd = 0; dd < DH; dd++) acc += qsh[h * DH + dd] * kvp[dd * DH + lane];
    g_laob[(size_t)row * CH + tid] = __float2bfloat16(acc * zinv);
}

// ---------------- mem = bf16(memory + pos_embed) ----------------
__global__ void mem_add(const float* __restrict__ memory, const float* __restrict__ pos)
{
    int i4 = blockIdx.x * blockDim.x + threadIdx.x;
    const int PER_N = SK * CH / 4;
    int p4 = i4 % PER_N;
    float4 a = ((const float4*)memory)[i4];
    float4 b = ((const float4*)pos)[p4];
    uint32_t lo = pack_bf16(a.x + b.x, a.y + b.y);
    uint32_t hi = pack_bf16(a.z + b.z, a.w + b.w);
    ((uint2*)g_memb)[i4] = make_uint2(lo, hi);
}

// ---------------- V transpose per (n,h): [s][d] -> [d][s] ----------------
__global__ void vtrans()
{
    __shared__ __nv_bfloat16 t[32][33];
    int s0 = blockIdx.x * 32;
    int nh = blockIdx.y;
    int n = nh >> 3, h = nh & 7;
    int tx = threadIdx.x, ty = threadIdx.y;   // (32,8)
    #pragma unroll
    for (int i = 0; i < 4; i++)
        t[ty + i * 8][tx] = g_cvb[(size_t)(n * SK + s0 + ty + i * 8) * CH + h * DH + tx];
    __syncthreads();
    #pragma unroll
    for (int i = 0; i < 4; i++)
        g_cvt[(size_t)(nh * DH + ty + i * 8) * SK + s0 + tx] = t[tx][ty + i * 8];
}

// ---------------- flash attention: 256q x 64s tiles, 16 warps, 3-stage, ldmatrix ----------------
// Doubling the q-block halves the K/V cp.async op count (the measured bottleneck).
__global__ void __launch_bounds__(512)
flash_attn_mma()
{
    __shared__ __nv_bfloat16 Qs[256][36];
    __shared__ __nv_bfloat16 Ks[3][64][40];
    __shared__ __nv_bfloat16 Vs[3][32][72];
    int tid = threadIdx.x;               // 512
    int lane = tid & 31, wid = tid >> 5; // 16 warps
    int qd = lane & 3, rg = lane >> 2;
    int qb = blockIdx.x * 256, h = blockIdx.y, n = blockIdx.z;
    int nh = n * NH + h;
    const float scale = 0.17677669529663687f;   // 32^-0.5

    #pragma unroll
    for (int i = 0; i < 8; i++) {
        int idx = tid + i * 512;          // 0..4095
        int r = idx >> 4, dp = idx & 15;
        uint32_t v = *(const uint32_t*)&g_cqb[(size_t)(n * LQ + qb + r) * CH + h * DH + dp * 2];
        *(uint32_t*)&Qs[r][dp * 2] = v;
    }

    int kr = tid >> 2, kc = (tid & 3) * 8;    // valid for tid<256
    int vr = tid >> 3, vc = (tid & 7) * 8;    // valid for tid<256
    const int T = SK / 64;
    #pragma unroll
    for (int pt = 0; pt < 2; pt++) {
        int sb = pt * 64;
        if (tid < 256) {
            CP16(saddr(&Ks[pt][kr][kc]), g_ckb + (size_t)(n * SK + sb + kr) * CH + h * DH + kc);
            CP16(saddr(&Vs[pt][vr][vc]), g_cvt + (size_t)(nh * DH + vr) * SK + sb + vc);
        }
        CP_COMMIT();
    }
    __syncthreads();   // Qs visible

    int r0 = wid * 16 + rg;
    uint32_t aq[2][4];
    #pragma unroll
    for (int ks = 0; ks < 2; ks++) {
        aq[ks][0] = *(uint32_t*)&Qs[r0    ][ks * 16 + qd * 2];
        aq[ks][1] = *(uint32_t*)&Qs[r0 + 8][ks * 16 + qd * 2];
        aq[ks][2] = *(uint32_t*)&Qs[r0    ][ks * 16 + qd * 2 + 8];
        aq[ks][3] = *(uint32_t*)&Qs[r0 + 8][ks * 16 + qd * 2 + 8];
    }

    int laneK = ((lane & 7) + (lane >> 4) * 8) * 40 + ((lane >> 3) & 1) * 8;
    int laneV = ((lane & 7) + (lane >> 4) * 8) * 72 + ((lane >> 3) & 1) * 8;

    float m0 = -1e30f, m1 = -1e30f, l0 = 0.f, l1 = 0.f;
    float o[4][4] = {};

    for (int kt = 0; kt < T; kt++) {
        CP_WAIT1();
        __syncthreads();
        int st = kt % 3;

        float sc[8][4];
        #pragma unroll
        for (int j = 0; j < 8; j++)
            #pragma unroll
            for (int e = 0; e < 4; e++) sc[j][e] = 0.f;
        uint32_t kb = saddr(&Ks[st][0][0]) + 2 * laneK;
        #pragma unroll
        for (int ks = 0; ks < 2; ks++) {
            #pragma unroll
            for (int jj = 0; jj < 4; jj++) {
                uint32_t b0, b1, b2, b3;
                ldsm4(b0, b1, b2, b3, kb + 2 * (jj * 16 * 40 + ks * 16));
                mma_bf16(sc[2 * jj    ], aq[ks][0], aq[ks][1], aq[ks][2], aq[ks][3], b0, b1);
                mma_bf16(sc[2 * jj + 1], aq[ks][0], aq[ks][1], aq[ks][2], aq[ks][3], b2, b3);
            }
        }

        float rm0 = -1e30f, rm1 = -1e30f;
        #pragma unroll
        for (int j = 0; j < 8; j++) {
            rm0 = fmaxf(rm0, fmaxf(sc[j][0], sc[j][1]));
            rm1 = fmaxf(rm1, fmaxf(sc[j][2], sc[j][3]));
        }
        rm0 = fmaxf(rm0, __shfl_xor_sync(0xffffffffu, rm0, 1));
        rm0 = fmaxf(rm0, __shfl_xor_sync(0xffffffffu, rm0, 2));
        rm1 = fmaxf(rm1, __shfl_xor_sync(0xffffffffu, rm1, 1));
        rm1 = fmaxf(rm1, __shfl_xor_sync(0xffffffffu, rm1, 2));
        float mn0 = fmaxf(m0, rm0), mn1 = fmaxf(m1, rm1);
        float corr0 = __expf((m0 - mn0) * scale);
        float corr1 = __expf((m1 - mn1) * scale);
        float s0 = 0.f, s1 = 0.f;
        #pragma unroll
        for (int j = 0; j < 8; j++) {
            sc[j][0] = __expf((sc[j][0] - mn0) * scale);
            sc[j][1] = __expf((sc[j][1] - mn0) * scale);
            sc[j][2] = __expf((sc[j][2] - mn1) * scale);
            sc[j][3] = __expf((sc[j][3] - mn1) * scale);
            s0 += sc[j][0] + sc[j][1];
            s1 += sc[j][2] + sc[j][3];
        }
        s0 += __shfl_xor_sync(0xffffffffu, s0, 1);
        s0 += __shfl_xor_sync(0xffffffffu, s0, 2);
        s1 += __shfl_xor_sync(0xffffffffu, s1, 1);
        s1 += __shfl_xor_sync(0xffffffffu, s1, 2);
        l0 = l0 * corr0 + s0;
        l1 = l1 * corr1 + s1;
        m0 = mn0; m1 = mn1;
        #pragma unroll
        for (int dj = 0; dj < 4; dj++) {
            o[dj][0] *= corr0; o[dj][1] *= corr0;
            o[dj][2] *= corr1; o[dj][3] *= corr1;
        }

        uint32_t vb = saddr(&Vs[st][0][0]) + 2 * laneV;
        #pragma unroll
        for (int t = 0; t < 4; t++) {
            uint32_t pa0 = pack_bf16(sc[2 * t    ][0], sc[2 * t    ][1]);
            uint32_t pa1 = pack_bf16(sc[2 * t    ][2], sc[2 * t    ][3]);
            uint32_t pa2 = pack_bf16(sc[2 * t + 1][0], sc[2 * t + 1][1]);
            uint32_t pa3 = pack_bf16(sc[2 * t + 1][2], sc[2 * t + 1][3]);
            #pragma unroll
            for (int dd = 0; dd < 2; dd++) {
                uint32_t v0, v1, v2, v3;
                ldsm4(v0, v1, v2, v3, vb + 2 * (dd * 16 * 72 + t * 16));
                mma_bf16(o[2 * dd    ], pa0, pa1, pa2, pa3, v0, v1);
                mma_bf16(o[2 * dd + 1], pa0, pa1, pa2, pa3, v2, v3);
            }
        }

        if (kt + 2 < T) {
            int st2 = (kt + 2) % 3, sb = (kt + 2) * 64;
            if (tid < 256) {
                CP16(saddr(&Ks[st2][kr][kc]), g_ckb + (size_t)(n * SK + sb + kr) * CH + h * DH + kc);
                CP16(saddr(&Vs[st2][vr][vc]), g_cvt + (size_t)(nh * DH + vr) * SK + sb + vc);
            }
        }
        CP_COMMIT();
    }

    float inv0 = 1.f / l0, inv1 = 1.f / l1;
    #pragma unroll
    for (int dj = 0; dj < 4; dj++) {
        size_t b0 = (size_t)(n * LQ + qb + r0    ) * CH + h * DH + dj * 8 + qd * 2;
        size_t b1 = (size_t)(n * LQ + qb + r0 + 8) * CH + h * DH + dj * 8 + qd * 2;
        *(__nv_bfloat162*)&g_cob[b0] = __float22bfloat162_rn(make_float2(o[dj][0] * inv0, o[dj][1] * inv0));
        *(__nv_bfloat162*)&g_cob[b1] = __float22bfloat162_rn(make_float2(o[dj][2] * inv1, o[dj][3] * inv1));
    }
}

// ---------------- depthwise conv3 (along L) + bias + exact gelu (bf16 in/out) ----------------
__global__ void conv_gelu(const float* __restrict__ dwk, const float* __restrict__ dwb)
{
    int i = blockIdx.x * blockDim.x + threadIdx.x;
    int c = i & (HID - 1);
    int l = (i >> 10) & (LQ - 1);
    float k0 = dwk[c * 9 + 1];
    float k1 = dwk[c * 9 + 4];
    float k2 = dwk[c * 9 + 7];
    float v = __bfloat162float(g_hb[i]) * k1;
    if (l > 0)      v += __bfloat162float(g_hb[i - HID]) * k0;
    if (l < LQ - 1) v += __bfloat162float(g_hb[i + HID]) * k2;
    v += dwb[c];
    float out = 0.5f * v * (1.f + erff(v * 0.70710678118654752f));
    g_h2b[i] = __float2bfloat16(out);
}

// ---------------- host ----------------
extern "C" void kernel_launch(void* const* d_in, const int* in_sizes, int n_in,
                              void* d_out, int out_size)
{
    const float* tgt      = (const float*)d_in[0];
    const float* memory   = (const float*)d_in[1];
    const float* tgt_pos  = (const float*)d_in[2];
    const float* pos_emb  = (const float*)d_in[3];
    const float* ln1_g = (const float*)d_in[4],  *ln1_b = (const float*)d_in[5];
    const float* ln2_g = (const float*)d_in[6],  *ln2_b = (const float*)d_in[7];
    const float* ln3_g = (const float*)d_in[8],  *ln3_b = (const float*)d_in[9];
    const float* wq = (const float*)d_in[10], *bq = (const float*)d_in[11];
    const float* wk = (const float*)d_in[12], *bk = (const float*)d_in[13];
    const float* wv = (const float*)d_in[14], *bv = (const float*)d_in[15];
    const float* w_merge = (const float*)d_in[16];
    const float* cwq = (const float*)d_in[17], *cbq = (const float*)d_in[18];
    const float* cwk = (const float*)d_in[19], *cbk = (const float*)d_in[20];
    const float* cwv = (const float*)d_in[21], *cbv = (const float*)d_in[22];
    const float* cwo = (const float*)d_in[23], *cbo = (const float*)d_in[24];
    const float* mw1 = (const float*)d_in[25], *mb1 = (const float*)d_in[26];
    const float* dwk = (const float*)d_in[27], *dwb = (const float*)d_in[28];
    const float* mw2 = (const float*)d_in[29], *mb2 = (const float*)d_in[30];
    float* out = (float*)d_out;

    float *p_q, *p_k, *p_v, *p_t1, *p_t2;
    __nv_bfloat16 *p_xb1, *p_xb2, *p_laob, *p_memb, *p_cqb, *p_ckb, *p_cvb, *p_cob, *p_hb, *p_h2b, *p_wts;
    cudaGetSymbolAddress((void**)&p_q,    g_q);
    cudaGetSymbolAddress((void**)&p_k,    g_k);
    cudaGetSymbolAddress((void**)&p_v,    g_v);
    cudaGetSymbolAddress((void**)&p_t1,   g_t1);
    cudaGetSymbolAddress((void**)&p_t2,   g_t2);
    cudaGetSymbolAddress((void**)&p_xb1,  g_xb1);
    cudaGetSymbolAddress((void**)&p_xb2,  g_xb2);
    cudaGetSymbolAddress((void**)&p_laob, g_laob);
    cudaGetSymbolAddress((void**)&p_memb, g_memb);
    cudaGetSymbolAddress((void**)&p_cqb,  g_cqb);
    cudaGetSymbolAddress((void**)&p_ckb,  g_ckb);
    cudaGetSymbolAddress((void**)&p_cvb,  g_cvb);
    cudaGetSymbolAddress((void**)&p_cob,  g_cob);
    cudaGetSymbolAddress((void**)&p_hb,   g_hb);
    cudaGetSymbolAddress((void**)&p_h2b,  g_h2b);
    cudaGetSymbolAddress((void**)&p_wts,  g_wts);

    // dynamic smem: 4 tiles (2 stages x A/B) * 128*136*2 B = 139264
    const int SM4 = 4 * TILE4 * 2;
    cudaFuncSetAttribute(gemm_v4<1, false, true>,  cudaFuncAttributeMaxDynamicSharedMemorySize, SM4);
    cudaFuncSetAttribute(gemm_v4<0, false, false>, cudaFuncAttributeMaxDynamicSharedMemorySize, SM4);
    cudaFuncSetAttribute(gemm_v4<2, false, false>, cudaFuncAttributeMaxDynamicSharedMemorySize, SM4);
    cudaFuncSetAttribute(gemm_v4<0, true, false>,  cudaFuncAttributeMaxDynamicSharedMemorySize, SM4);
    cudaFuncSetAttribute(gemm_v4<0, true, true>,   cudaFuncAttributeMaxDynamicSharedMemorySize, SM4);

    // ---- fused weight transpose (1 launch) ----
    WSrc ws;
    ws.p[0] = wq;  ws.p[1] = wk;  ws.p[2] = wv;  ws.p[3] = w_merge;
    ws.p[4] = cwq; ws.p[5] = cwk; ws.p[6] = cwv; ws.p[7] = cwo;
    ws.p[8] = mw1; ws.p[9] = mw2;
    wtrans_all<<<1024, dim3(32, 8)>>>(ws, p_wts);

    dim3 gq(CH / 128, NLROWS / 128);         // (2,64)
    dim3 gdual(2 * CH / 128, NLROWS / 128);  // (4,64)
    dim3 gmemd(2 * CH / 128, NSROWS / 128);  // (4,128)
    dim3 gm1(HID / 128, NLROWS / 128);       // (8,64)

    // ---- self attention (linear attention) ----
    ln_kernel<<<NLROWS, 256>>>(tgt, ln1_g, ln1_b, tgt_pos, p_xb1, p_xb2);
    gemm_v4<1, false, true><<<gdual, 256, SM4>>>(p_xb2, p_wts + WT_WQ, bq, bk, nullptr,
                                                 p_q, p_k, NLROWS, CH, CH);
    gemm_v4<0, false, false><<<gq, 256, SM4>>>(p_xb1, p_wts + WT_WV, bv, nullptr, nullptr,
                                               p_v, nullptr, NLROWS, CH, CH);
    kv_accum<<<dim3(NB * NH, 8), 1024>>>();
    kv_reduce<<<NB * NH, 1024>>>();
    lin_out<<<NLROWS, 256>>>();
    gemm_v4<2, false, false><<<gq, 256, SM4>>>(p_laob, p_wts + WT_WM, nullptr, nullptr, tgt,
                                               p_t1, nullptr, NLROWS, CH, CH);

    // ---- cross attention ----
    ln_kernel<<<NLROWS, 256>>>(p_t1, ln2_g, ln2_b, nullptr, p_xb1, nullptr);
    mem_add<<<NSROWS * CH / 4 / 256, 256>>>(memory, pos_emb);
    gemm_v4<0, true, false><<<gq, 256, SM4>>>(p_xb1, p_wts + WT_CWQ, cbq, nullptr, nullptr,
                                              p_cqb, nullptr, NLROWS, CH, CH);
    gemm_v4<0, true, true><<<gmemd, 256, SM4>>>(p_memb, p_wts + WT_CWK, cbk, cbv, nullptr,
                                                p_ckb, p_cvb, NSROWS, CH, CH);
    vtrans<<<dim3(SK / 32, NB * NH), dim3(32, 8)>>>();
    flash_attn_mma<<<dim3(LQ / 256, NH, NB), 512>>>();
    gemm_v4<2, false, false><<<gq, 256, SM4>>>(p_cob, p_wts + WT_CWO, cbo, nullptr, p_t1,
                                               p_t2, nullptr, NLROWS, CH, CH);

    // ---- MLP ----
    ln_kernel<<<NLROWS, 256>>>(p_t2, ln3_g, ln3_b, nullptr, p_xb1, nullptr);
    gemm_v4<0, true, false><<<gm1, 256, SM4>>>(p_xb1, p_wts + WT_MW1, mb1, nullptr, nullptr,
                                               p_hb, nullptr, NLROWS, CH, HID);
    conv_gelu<<<NLROWS * HID / 256, 256>>>(dwk, dwb);
    gemm_v4<2, false, false><<<gq, 256, SM4>>>(p_h2b, p_wts + WT_MW2, mb2, nullptr, p_t2,
                                               out, nullptr, NLROWS, HID, CH);
}